// round 10
// baseline (speedup 1.0000x reference)
#include <cuda_runtime.h>
#include <cuda_fp16.h>
#include <math.h>
#include <float.h>

#define NLAT 64
#define NLON 128
#define GPTS 8192   // NLAT*NLON
#define NS   1024   // stations
#define HD   256    // hidden dim
#define NB   2      // batch

// fp32 logits, [b][g][s]
__device__ float g_L[(size_t)NB * GPTS * NS];
// split-fp16 normalized weights, [b][g][s]
__device__ __half g_Ph[(size_t)NB * GPTS * NS];
__device__ __half g_Pl[(size_t)NB * GPTS * NS];
// fp16 transposed features (high part only), [b][d][s]
__device__ __half g_Fh[(size_t)NB * HD * NS];

// ---------------------------------------------------------------------------
// helpers
// ---------------------------------------------------------------------------
__device__ __forceinline__ float tanhap(float x)
{ float t; asm("tanh.approx.f32 %0, %1;" : "=f"(t) : "f"(x)); return t; }

__device__ __forceinline__ float sqrtap(float x)
{ float r; asm("sqrt.approx.f32 %0, %1;" : "=f"(r) : "f"(x)); return r; }

__device__ __forceinline__ unsigned smem_u32(const void* p)
{
    unsigned a;
    asm("{ .reg .u64 t; cvta.to.shared.u64 t, %1; cvt.u32.u64 %0, t; }"
        : "=r"(a) : "l"(p));
    return a;
}

__device__ __forceinline__ void split_fp16(float v, unsigned short& h, unsigned short& l)
{
    const __half hb = __float2half_rn(v);
    const float hf = __half2float(hb);
    const __half lb = __float2half_rn(v - hf);
    h = __half_as_ushort(hb);
    l = __half_as_ushort(lb);
}

__device__ __forceinline__ unsigned long long pack4(unsigned short a, unsigned short b,
                                                    unsigned short c, unsigned short d)
{
    return (unsigned long long)a | ((unsigned long long)b << 16)
         | ((unsigned long long)c << 32) | ((unsigned long long)d << 48);
}

// nonlinear GELU contribution: y*tanh(u) with y = z*v
__device__ __forceinline__ void unit_eval(float dist, float dlon,
                                          float w0, float wo, float a, float v,
                                          float& acc)
{
    const float z  = fmaf(dist, w0, fmaf(dlon, wo, a));
    const float y  = z * v;
    const float z2 = z * z;
    const float u  = z * fmaf(z2, 0.0356774081f, 0.7978845608f);
    acc = fmaf(y, tanhap(u), acc);
}

// ---------------------------------------------------------------------------
// F transpose: F[b][s][d] fp32 -> Fh [b][d][s] fp16 (high part only).
// ---------------------------------------------------------------------------
__global__ __launch_bounds__(256) void fsplit_kernel(const float* __restrict__ F)
{
    __shared__ float tile[64][65];
    const int t  = threadIdx.x;
    const int s0 = blockIdx.x * 64;
    const int d0 = blockIdx.y * 64;
    const int b  = blockIdx.z;

#pragma unroll
    for (int q = 0; q < 4; q++) {
        const int idx   = q * 256 + t;
        const int s_loc = idx >> 4;
        const int d4    = (idx & 15) * 4;
        const float4 v = *(const float4*)(F + ((size_t)(b * NS + s0 + s_loc)) * HD + d0 + d4);
        tile[s_loc][d4 + 0] = v.x;
        tile[s_loc][d4 + 1] = v.y;
        tile[s_loc][d4 + 2] = v.z;
        tile[s_loc][d4 + 3] = v.w;
    }
    __syncthreads();

#pragma unroll
    for (int q = 0; q < 4; q++) {
        const int idx   = q * 256 + t;
        const int d_loc = idx >> 4;
        const int s4    = (idx & 15) * 4;
        unsigned short h[4];
#pragma unroll
        for (int e = 0; e < 4; e++)
            h[e] = __half_as_ushort(__float2half_rn(tile[s4 + e][d_loc]));
        const size_t off = ((size_t)(b * HD + d0 + d_loc)) * NS + s0 + s4;
        *(unsigned long long*)(g_Fh + off) = pack4(h[0], h[1], h[2], h[3]);
    }
}

// ---------------------------------------------------------------------------
// Phase 1: logits + fused online softmax, per batch (b passed as arg).
// Grid (GPTS/32), 256 threads = 8 warps.
// ---------------------------------------------------------------------------
__global__ __launch_bounds__(256) void weights_kernel(
    const float* __restrict__ coords,   // [B, S, 3]
    const float* __restrict__ mask,     // [B, S]
    const float* __restrict__ W1,       // [3, 32]
    const float* __restrict__ b1,       // [32]
    const float* __restrict__ W2,       // [32, 1]
    const float* __restrict__ b2,       // [1]
    const int b)
{
    __shared__ __align__(16) float sW0[32];
    __shared__ __align__(16) float sWa[32];
    __shared__ __align__(16) float sWo[32];
    __shared__ __align__(16) float sB1[32];
    __shared__ __align__(16) float sV[32];           // W2/2
    __shared__ __align__(16) float sA[8][2][2][32];  // [warp][buf][station][unit]
    __shared__ float sLat[NS];
    __shared__ float sLon[NS];
    __shared__ float sMask[NS];
    __shared__ float sS0, sSa, sSo, sSbb;
    __shared__ float red_m[8][32];
    __shared__ float red_s[8][32];
    __shared__ float sT[8][32][33];
    __shared__ float sMax[32];
    __shared__ float sInv[32];

    const int tid  = threadIdx.x;
    const int lane = tid & 31;
    const int wrp  = tid >> 5;
    const int g0   = blockIdx.x * 32;
    const size_t bG = (size_t)b * GPTS;

    if (tid < 32) {
        sW0[tid] = W1[tid];
        sWa[tid] = W1[32 + tid];
        sWo[tid] = W1[64 + tid];
        sB1[tid] = b1[tid];
        sV[tid]  = 0.5f * W2[tid];
    }

    for (int s = tid; s < NS; s += 256) {
        sLat[s]  = coords[((size_t)b * NS + s) * 3 + 0];
        sLon[s]  = coords[((size_t)b * NS + s) * 3 + 1];
        sMask[s] = mask[(size_t)b * NS + s];
    }
    __syncthreads();

    if (wrp == 0) {
        const float v = sV[lane];
        float p0 = sW0[lane] * v;
        float pa = sWa[lane] * v;
        float po = sWo[lane] * v;
        float pb = sB1[lane] * v;
#pragma unroll
        for (int off = 16; off > 0; off >>= 1) {
            p0 += __shfl_xor_sync(0xffffffffu, p0, off);
            pa += __shfl_xor_sync(0xffffffffu, pa, off);
            po += __shfl_xor_sync(0xffffffffu, po, off);
            pb += __shfl_xor_sync(0xffffffffu, pb, off);
        }
        if (lane == 0) {
            sS0 = p0; sSa = pa; sSo = po; sSbb = pb + b2[0];
        }
    }
    __syncthreads();

    const int g = g0 + lane;
    const float glat = -90.0f  + (float)(g >> 7)  * (180.0f / 63.0f);  // warp-uniform
    const float glon = -180.0f + (float)(g & 127) * (360.0f / 127.0f);

    const float S0v = sS0, Sav = sSa, Sov = sSo, Sbb = sSbb;
    const float wa_l = sWa[lane];
    const float b1_l = sB1[lane];

    float m_run = -FLT_MAX;
    float s_run = 0.0f;
    const int s_base = wrp * 128;

#pragma unroll 1
    for (int it = 0; it < 128; it += 2) {
        const int s0 = s_base + it;
        const int s1 = s0 + 1;
        const int buf = (it >> 1) & 1;

        const float dlat0 = sLat[s0] - glat;
        const float dlon0 = sLon[s0] - glon;
        const float dist0 = sqrtap(fmaf(dlat0, dlat0, fmaf(dlon0, dlon0, 1e-6f)));
        const float dlat1 = sLat[s1] - glat;
        const float dlon1 = sLon[s1] - glon;
        const float dist1 = sqrtap(fmaf(dlat1, dlat1, fmaf(dlon1, dlon1, 1e-6f)));

        sA[wrp][buf][0][lane] = fmaf(dlat0, wa_l, b1_l);
        sA[wrp][buf][1][lane] = fmaf(dlat1, wa_l, b1_l);
        __syncwarp();

        float acc0 = 0.0f;
        float acc1 = 0.0f;
        const float lin0 = fmaf(dist0, S0v, fmaf(dlon0, Sov, fmaf(dlat0, Sav, Sbb)));
        const float lin1 = fmaf(dist1, S0v, fmaf(dlon1, Sov, fmaf(dlat1, Sav, Sbb)));

#pragma unroll
        for (int q = 0; q < 8; q++) {
            const float4 w0 = *(const float4*)&sW0[4 * q];
            const float4 wo = *(const float4*)&sWo[4 * q];
            const float4 vv = *(const float4*)&sV[4 * q];
            const float4 a0 = *(const float4*)&sA[wrp][buf][0][4 * q];
            const float4 a1 = *(const float4*)&sA[wrp][buf][1][4 * q];

            unit_eval(dist0, dlon0, w0.x, wo.x, a0.x, vv.x, acc0);
            unit_eval(dist0, dlon0, w0.y, wo.y, a0.y, vv.y, acc0);
            unit_eval(dist0, dlon0, w0.z, wo.z, a0.z, vv.z, acc0);
            unit_eval(dist0, dlon0, w0.w, wo.w, a0.w, vv.w, acc0);

            unit_eval(dist1, dlon1, w0.x, wo.x, a1.x, vv.x, acc1);
            unit_eval(dist1, dlon1, w0.y, wo.y, a1.y, vv.y, acc1);
            unit_eval(dist1, dlon1, w0.z, wo.z, a1.z, vv.z, acc1);
            unit_eval(dist1, dlon1, w0.w, wo.w, a1.w, vv.w, acc1);
        }

        const float pre0 = lin0 + acc0;
        const float pre1 = lin1 + acc1;

        const float sp0 = fmaxf(pre0, 0.0f) + __logf(1.0f + __expf(-fabsf(pre0)));
        const float sp1 = fmaxf(pre1, 0.0f) + __logf(1.0f + __expf(-fabsf(pre1)));
        const float l0  = sp0 * sMask[s0];
        const float l1  = sp1 * sMask[s1];

        const float mnew = fmaxf(m_run, fmaxf(l0, l1));
        s_run = fmaf(s_run, __expf(m_run - mnew),
                     __expf(l0 - mnew) + __expf(l1 - mnew));
        m_run = mnew;

        const int c0 = it & 31;
        sT[wrp][lane][c0]     = l0;
        sT[wrp][lane][c0 + 1] = l1;

        if (c0 == 30) {
            __syncwarp();
            const int sblk = s_base + (it & ~31);
#pragma unroll
            for (int r = 0; r < 32; r++)
                g_L[(bG + g0 + r) * NS + sblk + lane] = sT[wrp][r][lane];
            __syncwarp();
        }
    }

    red_m[wrp][lane] = m_run;
    red_s[wrp][lane] = s_run;
    __syncthreads();

    float M = -FLT_MAX;
#pragma unroll
    for (int w = 0; w < 8; w++) M = fmaxf(M, red_m[w][lane]);
    float Stot = 0.0f;
#pragma unroll
    for (int w = 0; w < 8; w++) Stot += red_s[w][lane] * __expf(red_m[w][lane] - M);

    if (wrp == 0) {
        sMax[lane] = M;
        sInv[lane] = 1.0f / Stot;
    }
    __syncthreads();

    // normalize pass: each warp handles 4 g-rows; emit split fp16 [g][s].
#pragma unroll 1
    for (int k = 0; k < 4; k++) {
        const int r  = wrp + 8 * k;
        const float Mr   = sMax[r];
        const float invr = sInv[r];
        const size_t row = (bG + g0 + r) * NS;
#pragma unroll
        for (int cc = 0; cc < 8; cc++) {
            const int s4 = cc * 128 + lane * 4;
            const float4 v = *(const float4*)(g_L + row + s4);
            unsigned short h[4], l[4];
            split_fp16(__expf(v.x - Mr) * invr, h[0], l[0]);
            split_fp16(__expf(v.y - Mr) * invr, h[1], l[1]);
            split_fp16(__expf(v.z - Mr) * invr, h[2], l[2]);
            split_fp16(__expf(v.w - Mr) * invr, h[3], l[3]);
            *(unsigned long long*)(g_Ph + row + s4) = pack4(h[0], h[1], h[2], h[3]);
            *(unsigned long long*)(g_Pl + row + s4) = pack4(l[0], l[1], l[2], l[3]);
        }
    }
}

// ---------------------------------------------------------------------------
// Phase 2: fp16 2-product HMMA GEMM (Fh*Ph + Fh*Pl), 3-stage cp.async.
// Per-batch launch (b arg). Block: 128d x 128g x BK32, 256 threads (8 warps),
// warp tile 64d x 32g. smem 92KB -> co-resident with weights CTAs.
// ---------------------------------------------------------------------------
#define GBK   32
#define ROWB  80
#define GA_H  0
#define GB_H  10240
#define GB_L  20480
#define GST   30720
#define GSM_TOTAL (3 * GST)

__device__ __forceinline__ void cpa16(unsigned dst, const void* src)
{
    asm volatile("cp.async.cg.shared.global [%0], [%1], 16;"
                 :: "r"(dst), "l"(__cvta_generic_to_global(src)));
}

__device__ __forceinline__ void ldsm4(unsigned* r, unsigned addr)
{
    asm volatile("ldmatrix.sync.aligned.m8n8.x4.shared.b16 {%0,%1,%2,%3}, [%4];"
                 : "=r"(r[0]), "=r"(r[1]), "=r"(r[2]), "=r"(r[3]) : "r"(addr));
}

__device__ __forceinline__ void mma16816(float* c, const unsigned* a, unsigned b0, unsigned b1)
{
    asm volatile(
        "mma.sync.aligned.m16n8k16.row.col.f32.f16.f16.f32 "
        "{%0,%1,%2,%3}, {%4,%5,%6,%7}, {%8,%9}, {%0,%1,%2,%3};"
        : "+f"(c[0]), "+f"(c[1]), "+f"(c[2]), "+f"(c[3])
        : "r"(a[0]), "r"(a[1]), "r"(a[2]), "r"(a[3]), "r"(b0), "r"(b1));
}

__global__ __launch_bounds__(256, 1) void hmma_gemm_kernel(float* __restrict__ out,
                                                           const int b)
{
    extern __shared__ __align__(16) char smem[];
    const unsigned sb = smem_u32(smem);

    const int t    = threadIdx.x;
    const int wid  = t >> 5;
    const int lane = t & 31;
    const int g0   = blockIdx.x * 128;
    const int d0   = blockIdx.y * 128;

    const int wm = wid & 1;        // d half (64)
    const int wn = wid >> 1;       // g slice of 32 (0..3)
    const int gid = lane >> 2;
    const int tig = lane & 3;

    // fill mapping: 512 16B-chunks per tile, 2 per thread (rows fr, fr+64)
    const int fr = t >> 2;         // 0..63
    const int fp = t & 3;          // 0..3
    const unsigned dst0 = (unsigned)(fr * ROWB + fp * 16);
    const unsigned dst1 = (unsigned)((fr + 64) * ROWB + fp * 16);

    const __half* FA0 = g_Fh + ((size_t)(b * HD + d0 + fr)) * NS + fp * 8;
    const __half* FA1 = FA0 + (size_t)64 * NS;
    const __half* PH0 = g_Ph + ((size_t)b * GPTS + g0 + fr) * NS + fp * 8;
    const __half* PH1 = PH0 + (size_t)64 * NS;
    const __half* PL0 = g_Pl + ((size_t)b * GPTS + g0 + fr) * NS + fp * 8;
    const __half* PL1 = PL0 + (size_t)64 * NS;

    const int NC = NS / GBK;   // 32

#pragma unroll
    for (int p = 0; p < 2; p++) {
        const unsigned sn = sb + (unsigned)(p * GST);
        const int sc = p * GBK;
        cpa16(sn + GA_H + dst0, FA0 + sc);
        cpa16(sn + GA_H + dst1, FA1 + sc);
        cpa16(sn + GB_H + dst0, PH0 + sc);
        cpa16(sn + GB_H + dst1, PH1 + sc);
        cpa16(sn + GB_L + dst0, PL0 + sc);
        cpa16(sn + GB_L + dst1, PL1 + sc);
        asm volatile("cp.async.commit_group;");
    }

    float acc[4][4][4];
#pragma unroll
    for (int i = 0; i < 4; i++)
#pragma unroll
        for (int j = 0; j < 4; j++)
#pragma unroll
            for (int e = 0; e < 4; e++) acc[i][j][e] = 0.0f;

    const unsigned am_row = (unsigned)((lane & 7) + ((lane >> 3) & 1) * 8);
    const unsigned am_kh  = (unsigned)(lane >> 4);
    const unsigned bm_row = (unsigned)(((lane >> 4) & 1) * 8 + (lane & 7));
    const unsigned bm_kb  = (unsigned)(((lane >> 3) & 1) * 16);

    int stage = 0;
#pragma unroll 1
    for (int c = 0; c < NC; c++) {
        const unsigned st = sb + (unsigned)(stage * GST);

        if (c + 1 < NC) asm volatile("cp.async.wait_group 1;");
        else            asm volatile("cp.async.wait_group 0;");
        __syncthreads();

        if (c + 2 < NC) {
            int pst = stage + 2; if (pst >= 3) pst -= 3;
            const unsigned sn = sb + (unsigned)(pst * GST);
            const int sc = (c + 2) * GBK;
            cpa16(sn + GA_H + dst0, FA0 + sc);
            cpa16(sn + GA_H + dst1, FA1 + sc);
            cpa16(sn + GB_H + dst0, PH0 + sc);
            cpa16(sn + GB_H + dst1, PH1 + sc);
            cpa16(sn + GB_L + dst0, PL0 + sc);
            cpa16(sn + GB_L + dst1, PL1 + sc);
            asm volatile("cp.async.commit_group;");
        }

#pragma unroll
        for (int kk = 0; kk < 2; kk++) {
            const unsigned kb = (unsigned)(kk * 16 + am_kh * 8) * 2;

            unsigned ah[4][4];
#pragma unroll
            for (int i = 0; i < 4; i++) {
                const unsigned rowoff = (unsigned)(wm * 64 + i * 16) + am_row;
                ldsm4(ah[i], st + GA_H + rowoff * ROWB + kb);
            }

#pragma unroll
            for (int jp = 0; jp < 2; jp++) {
                const unsigned brow = (unsigned)(wn * 32 + jp * 16) + bm_row;
                const unsigned bcol = (unsigned)(kk * 32) + bm_kb;
                unsigned bh[4], bl[4];
                ldsm4(bh, st + GB_H + brow * ROWB + bcol);
                ldsm4(bl, st + GB_L + brow * ROWB + bcol);
#pragma unroll
                for (int jj = 0; jj < 2; jj++) {
                    const int j = jp * 2 + jj;
#pragma unroll
                    for (int i = 0; i < 4; i++) {
                        mma16816(acc[i][j], ah[i], bh[2*jj], bh[2*jj+1]);
                        mma16816(acc[i][j], ah[i], bl[2*jj], bl[2*jj+1]);
                    }
                }
            }
        }

        if (++stage >= 3) stage = 0;
    }

    // epilogue: out[b][d][g]
    float* ob = out + (size_t)b * HD * GPTS;
#pragma unroll
    for (int i = 0; i < 4; i++) {
        const int d_r = d0 + wm * 64 + i * 16 + gid;
#pragma unroll
        for (int j = 0; j < 4; j++) {
            const int g_c = g0 + wn * 32 + j * 8 + tig * 2;
            *(float2*)(ob + (size_t)d_r * GPTS + g_c) =
                make_float2(acc[i][j][0], acc[i][j][1]);
            *(float2*)(ob + (size_t)(d_r + 8) * GPTS + g_c) =
                make_float2(acc[i][j][2], acc[i][j][3]);
        }
    }
}

// ---------------------------------------------------------------------------
// kernel_launch — fork/join pipeline: GEMM(b) overlaps weights(b+1).
// Inputs: station_features, station_coords, mask, W1, b1, W2, b2
// ---------------------------------------------------------------------------
extern "C" void kernel_launch(void* const* d_in, const int* in_sizes, int n_in,
                              void* d_out, int out_size)
{
    const float* features = (const float*)d_in[0];  // [2,1024,256]
    const float* coords   = (const float*)d_in[1];  // [2,1024,3]
    const float* mask     = (const float*)d_in[2];  // [2,1024]
    const float* W1       = (const float*)d_in[3];  // [3,32]
    const float* b1       = (const float*)d_in[4];  // [32]
    const float* W2       = (const float*)d_in[5];  // [32,1]
    const float* b2       = (const float*)d_in[6];  // [1]
    float* out            = (float*)d_out;          // [2,256,64,128]

    static cudaStream_t sB = nullptr;
    static cudaEvent_t evW0 = nullptr, evW1 = nullptr, evDone = nullptr;
    if (!sB) {
        cudaStreamCreateWithFlags(&sB, cudaStreamNonBlocking);
        cudaEventCreateWithFlags(&evW0,   cudaEventDisableTiming);
        cudaEventCreateWithFlags(&evW1,   cudaEventDisableTiming);
        cudaEventCreateWithFlags(&evDone, cudaEventDisableTiming);
        cudaFuncSetAttribute(hmma_gemm_kernel,
                             cudaFuncAttributeMaxDynamicSharedMemorySize, GSM_TOTAL);
    }

    dim3 gf(NS / 64, HD / 64, NB);
    fsplit_kernel<<<gf, 256>>>(features);

    weights_kernel<<<GPTS / 32, 256>>>(coords, mask, W1, b1, W2, b2, 0);
    cudaEventRecord(evW0, 0);
    weights_kernel<<<GPTS / 32, 256>>>(coords, mask, W1, b1, W2, b2, 1);
    cudaEventRecord(evW1, 0);

    dim3 g2(GPTS / 128, HD / 128);
    cudaStreamWaitEvent(sB, evW0, 0);
    hmma_gemm_kernel<<<g2, 256, GSM_TOTAL, sB>>>(out, 0);
    cudaStreamWaitEvent(sB, evW1, 0);
    hmma_gemm_kernel<<<g2, 256, GSM_TOTAL, sB>>>(out, 1);
    cudaEventRecord(evDone, sB);
    cudaStreamWaitEvent((cudaStream_t)0, evDone, 0);
}

// round 11
// speedup vs baseline: 1.0492x; 1.0492x over previous
#include <cuda_runtime.h>
#include <cuda_fp16.h>
#include <math.h>
#include <float.h>

#define NLAT 64
#define NLON 128
#define GPTS 8192   // NLAT*NLON
#define NS   1024   // stations
#define HD   256    // hidden dim
#define NB   2      // batch

// fp32 logits, [b][g][s]
__device__ float g_L[(size_t)NB * GPTS * NS];
// split-fp16 normalized weights, [b][g][s]
__device__ __half g_Ph[(size_t)NB * GPTS * NS];
__device__ __half g_Pl[(size_t)NB * GPTS * NS];
// fp16 transposed features (high part only), [b][d][s]
__device__ __half g_Fh[(size_t)NB * HD * NS];

// ---------------------------------------------------------------------------
// helpers
// ---------------------------------------------------------------------------
__device__ __forceinline__ float tanhap(float x)
{ float t; asm("tanh.approx.f32 %0, %1;" : "=f"(t) : "f"(x)); return t; }

__device__ __forceinline__ float sqrtap(float x)
{ float r; asm("sqrt.approx.f32 %0, %1;" : "=f"(r) : "f"(x)); return r; }

__device__ __forceinline__ unsigned smem_u32(const void* p)
{
    unsigned a;
    asm("{ .reg .u64 t; cvta.to.shared.u64 t, %1; cvt.u32.u64 %0, t; }"
        : "=r"(a) : "l"(p));
    return a;
}

__device__ __forceinline__ void split_fp16(float v, unsigned short& h, unsigned short& l)
{
    const __half hb = __float2half_rn(v);
    const float hf = __half2float(hb);
    const __half lb = __float2half_rn(v - hf);
    h = __half_as_ushort(hb);
    l = __half_as_ushort(lb);
}

__device__ __forceinline__ unsigned long long pack4(unsigned short a, unsigned short b,
                                                    unsigned short c, unsigned short d)
{
    return (unsigned long long)a | ((unsigned long long)b << 16)
         | ((unsigned long long)c << 32) | ((unsigned long long)d << 48);
}

// nonlinear GELU contribution: y*tanh(u) with y = z*v
__device__ __forceinline__ void unit_eval(float dist, float dlon,
                                          float w0, float wo, float a, float v,
                                          float& acc)
{
    const float z  = fmaf(dist, w0, fmaf(dlon, wo, a));
    const float y  = z * v;
    const float z2 = z * z;
    const float u  = z * fmaf(z2, 0.0356774081f, 0.7978845608f);
    acc = fmaf(y, tanhap(u), acc);
}

// ---------------------------------------------------------------------------
// F transpose: F[b][s][d] fp32 -> Fh [b][d][s] fp16 (high part only).
// ---------------------------------------------------------------------------
__global__ __launch_bounds__(256) void fsplit_kernel(const float* __restrict__ F)
{
    __shared__ float tile[64][65];
    const int t  = threadIdx.x;
    const int s0 = blockIdx.x * 64;
    const int d0 = blockIdx.y * 64;
    const int b  = blockIdx.z;

#pragma unroll
    for (int q = 0; q < 4; q++) {
        const int idx   = q * 256 + t;
        const int s_loc = idx >> 4;
        const int d4    = (idx & 15) * 4;
        const float4 v = *(const float4*)(F + ((size_t)(b * NS + s0 + s_loc)) * HD + d0 + d4);
        tile[s_loc][d4 + 0] = v.x;
        tile[s_loc][d4 + 1] = v.y;
        tile[s_loc][d4 + 2] = v.z;
        tile[s_loc][d4 + 3] = v.w;
    }
    __syncthreads();

#pragma unroll
    for (int q = 0; q < 4; q++) {
        const int idx   = q * 256 + t;
        const int d_loc = idx >> 4;
        const int s4    = (idx & 15) * 4;
        unsigned short h[4];
#pragma unroll
        for (int e = 0; e < 4; e++)
            h[e] = __half_as_ushort(__float2half_rn(tile[s4 + e][d_loc]));
        const size_t off = ((size_t)(b * HD + d0 + d_loc)) * NS + s0 + s4;
        *(unsigned long long*)(g_Fh + off) = pack4(h[0], h[1], h[2], h[3]);
    }
}

// ---------------------------------------------------------------------------
// Phase 1: logits + fused online softmax.
// Grid (GPTS/32, NB), 256 threads = 8 warps.
// ---------------------------------------------------------------------------
__global__ __launch_bounds__(256) void weights_kernel(
    const float* __restrict__ coords,   // [B, S, 3]
    const float* __restrict__ mask,     // [B, S]
    const float* __restrict__ W1,       // [3, 32]
    const float* __restrict__ b1,       // [32]
    const float* __restrict__ W2,       // [32, 1]
    const float* __restrict__ b2)       // [1]
{
    __shared__ __align__(16) float sW0[32];
    __shared__ __align__(16) float sWa[32];
    __shared__ __align__(16) float sWo[32];
    __shared__ __align__(16) float sB1[32];
    __shared__ __align__(16) float sV[32];           // W2/2
    __shared__ __align__(16) float sA[8][2][2][32];  // [warp][buf][station][unit]
    __shared__ float sLat[NS];
    __shared__ float sLon[NS];
    __shared__ float sMask[NS];
    __shared__ float sS0, sSa, sSo, sSbb;
    __shared__ float red_m[8][32];
    __shared__ float red_s[8][32];
    __shared__ float sT[8][32][33];
    __shared__ float sMax[32];
    __shared__ float sInv[32];

    const int tid  = threadIdx.x;
    const int lane = tid & 31;
    const int wrp  = tid >> 5;
    const int b    = blockIdx.y;
    const int g0   = blockIdx.x * 32;
    const size_t bG = (size_t)b * GPTS;

    if (tid < 32) {
        sW0[tid] = W1[tid];
        sWa[tid] = W1[32 + tid];
        sWo[tid] = W1[64 + tid];
        sB1[tid] = b1[tid];
        sV[tid]  = 0.5f * W2[tid];
    }

    for (int s = tid; s < NS; s += 256) {
        sLat[s]  = coords[((size_t)b * NS + s) * 3 + 0];
        sLon[s]  = coords[((size_t)b * NS + s) * 3 + 1];
        sMask[s] = mask[(size_t)b * NS + s];
    }
    __syncthreads();

    if (wrp == 0) {
        const float v = sV[lane];
        float p0 = sW0[lane] * v;
        float pa = sWa[lane] * v;
        float po = sWo[lane] * v;
        float pb = sB1[lane] * v;
#pragma unroll
        for (int off = 16; off > 0; off >>= 1) {
            p0 += __shfl_xor_sync(0xffffffffu, p0, off);
            pa += __shfl_xor_sync(0xffffffffu, pa, off);
            po += __shfl_xor_sync(0xffffffffu, po, off);
            pb += __shfl_xor_sync(0xffffffffu, pb, off);
        }
        if (lane == 0) {
            sS0 = p0; sSa = pa; sSo = po; sSbb = pb + b2[0];
        }
    }
    __syncthreads();

    const int g = g0 + lane;
    const float glat = -90.0f  + (float)(g >> 7)  * (180.0f / 63.0f);  // warp-uniform
    const float glon = -180.0f + (float)(g & 127) * (360.0f / 127.0f);

    const float S0v = sS0, Sav = sSa, Sov = sSo, Sbb = sSbb;
    const float wa_l = sWa[lane];
    const float b1_l = sB1[lane];

    float m_run = -FLT_MAX;
    float s_run = 0.0f;
    const int s_base = wrp * 128;

#pragma unroll 1
    for (int it = 0; it < 128; it += 2) {
        const int s0 = s_base + it;
        const int s1 = s0 + 1;
        const int buf = (it >> 1) & 1;

        const float dlat0 = sLat[s0] - glat;
        const float dlon0 = sLon[s0] - glon;
        const float dist0 = sqrtap(fmaf(dlat0, dlat0, fmaf(dlon0, dlon0, 1e-6f)));
        const float dlat1 = sLat[s1] - glat;
        const float dlon1 = sLon[s1] - glon;
        const float dist1 = sqrtap(fmaf(dlat1, dlat1, fmaf(dlon1, dlon1, 1e-6f)));

        sA[wrp][buf][0][lane] = fmaf(dlat0, wa_l, b1_l);
        sA[wrp][buf][1][lane] = fmaf(dlat1, wa_l, b1_l);
        __syncwarp();

        float acc0 = 0.0f;
        float acc1 = 0.0f;
        const float lin0 = fmaf(dist0, S0v, fmaf(dlon0, Sov, fmaf(dlat0, Sav, Sbb)));
        const float lin1 = fmaf(dist1, S0v, fmaf(dlon1, Sov, fmaf(dlat1, Sav, Sbb)));

#pragma unroll
        for (int q = 0; q < 8; q++) {
            const float4 w0 = *(const float4*)&sW0[4 * q];
            const float4 wo = *(const float4*)&sWo[4 * q];
            const float4 vv = *(const float4*)&sV[4 * q];
            const float4 a0 = *(const float4*)&sA[wrp][buf][0][4 * q];
            const float4 a1 = *(const float4*)&sA[wrp][buf][1][4 * q];

            unit_eval(dist0, dlon0, w0.x, wo.x, a0.x, vv.x, acc0);
            unit_eval(dist0, dlon0, w0.y, wo.y, a0.y, vv.y, acc0);
            unit_eval(dist0, dlon0, w0.z, wo.z, a0.z, vv.z, acc0);
            unit_eval(dist0, dlon0, w0.w, wo.w, a0.w, vv.w, acc0);

            unit_eval(dist1, dlon1, w0.x, wo.x, a1.x, vv.x, acc1);
            unit_eval(dist1, dlon1, w0.y, wo.y, a1.y, vv.y, acc1);
            unit_eval(dist1, dlon1, w0.z, wo.z, a1.z, vv.z, acc1);
            unit_eval(dist1, dlon1, w0.w, wo.w, a1.w, vv.w, acc1);
        }

        const float pre0 = lin0 + acc0;
        const float pre1 = lin1 + acc1;

        const float sp0 = fmaxf(pre0, 0.0f) + __logf(1.0f + __expf(-fabsf(pre0)));
        const float sp1 = fmaxf(pre1, 0.0f) + __logf(1.0f + __expf(-fabsf(pre1)));
        const float l0  = sp0 * sMask[s0];
        const float l1  = sp1 * sMask[s1];

        const float mnew = fmaxf(m_run, fmaxf(l0, l1));
        s_run = fmaf(s_run, __expf(m_run - mnew),
                     __expf(l0 - mnew) + __expf(l1 - mnew));
        m_run = mnew;

        const int c0 = it & 31;
        sT[wrp][lane][c0]     = l0;
        sT[wrp][lane][c0 + 1] = l1;

        if (c0 == 30) {
            __syncwarp();
            const int sblk = s_base + (it & ~31);
#pragma unroll
            for (int r = 0; r < 32; r++)
                g_L[(bG + g0 + r) * NS + sblk + lane] = sT[wrp][r][lane];
            __syncwarp();
        }
    }

    red_m[wrp][lane] = m_run;
    red_s[wrp][lane] = s_run;
    __syncthreads();

    float M = -FLT_MAX;
#pragma unroll
    for (int w = 0; w < 8; w++) M = fmaxf(M, red_m[w][lane]);
    float Stot = 0.0f;
#pragma unroll
    for (int w = 0; w < 8; w++) Stot += red_s[w][lane] * __expf(red_m[w][lane] - M);

    if (wrp == 0) {
        sMax[lane] = M;
        sInv[lane] = 1.0f / Stot;
    }
    __syncthreads();

    // normalize pass: each warp handles 4 g-rows; emit split fp16 [g][s].
#pragma unroll 1
    for (int k = 0; k < 4; k++) {
        const int r  = wrp + 8 * k;
        const float Mr   = sMax[r];
        const float invr = sInv[r];
        const size_t row = (bG + g0 + r) * NS;
#pragma unroll
        for (int cc = 0; cc < 8; cc++) {
            const int s4 = cc * 128 + lane * 4;
            const float4 v = *(const float4*)(g_L + row + s4);
            unsigned short h[4], l[4];
            split_fp16(__expf(v.x - Mr) * invr, h[0], l[0]);
            split_fp16(__expf(v.y - Mr) * invr, h[1], l[1]);
            split_fp16(__expf(v.z - Mr) * invr, h[2], l[2]);
            split_fp16(__expf(v.w - Mr) * invr, h[3], l[3]);
            *(unsigned long long*)(g_Ph + row + s4) = pack4(h[0], h[1], h[2], h[3]);
            *(unsigned long long*)(g_Pl + row + s4) = pack4(l[0], l[1], l[2], l[3]);
        }
    }
}

// ---------------------------------------------------------------------------
// Phase 2: fp16 2-product HMMA GEMM (Fh*Ph + Fh*Pl), 3-stage cp.async.
// Block: 128d x 128g x BK32, 256 threads (8 warps), warp tile 64d x 32g.
// __launch_bounds__(256, 2): cap regs at 128 -> 2 CTAs/SM (16 warps) for
// latency hiding; smem 2 x 90KB = 180KB fits.
// Grid (GPTS/128, HD/128, NB) = 256 CTAs = one 2/SM wave.
// ---------------------------------------------------------------------------
#define GBK   32
#define ROWB  80
#define GA_H  0
#define GB_H  10240
#define GB_L  20480
#define GST   30720
#define GSM_TOTAL (3 * GST)

__device__ __forceinline__ void cpa16(unsigned dst, const void* src)
{
    asm volatile("cp.async.cg.shared.global [%0], [%1], 16;"
                 :: "r"(dst), "l"(__cvta_generic_to_global(src)));
}

__device__ __forceinline__ void ldsm4(unsigned* r, unsigned addr)
{
    asm volatile("ldmatrix.sync.aligned.m8n8.x4.shared.b16 {%0,%1,%2,%3}, [%4];"
                 : "=r"(r[0]), "=r"(r[1]), "=r"(r[2]), "=r"(r[3]) : "r"(addr));
}

__device__ __forceinline__ void mma16816(float* c, const unsigned* a, unsigned b0, unsigned b1)
{
    asm volatile(
        "mma.sync.aligned.m16n8k16.row.col.f32.f16.f16.f32 "
        "{%0,%1,%2,%3}, {%4,%5,%6,%7}, {%8,%9}, {%0,%1,%2,%3};"
        : "+f"(c[0]), "+f"(c[1]), "+f"(c[2]), "+f"(c[3])
        : "r"(a[0]), "r"(a[1]), "r"(a[2]), "r"(a[3]), "r"(b0), "r"(b1));
}

__global__ __launch_bounds__(256, 2) void hmma_gemm_kernel(float* __restrict__ out)
{
    extern __shared__ __align__(16) char smem[];
    const unsigned sb = smem_u32(smem);

    const int t    = threadIdx.x;
    const int wid  = t >> 5;
    const int lane = t & 31;
    const int g0   = blockIdx.x * 128;
    const int d0   = blockIdx.y * 128;
    const int b    = blockIdx.z;

    const int wm = wid & 1;        // d half (64)
    const int wn = wid >> 1;       // g slice of 32 (0..3)
    const int gid = lane >> 2;
    const int tig = lane & 3;

    // fill mapping: 512 16B-chunks per tile, 2 per thread (rows fr, fr+64)
    const int fr = t >> 2;         // 0..63
    const int fp = t & 3;          // 0..3
    const unsigned dst0 = (unsigned)(fr * ROWB + fp * 16);
    const unsigned dst1 = (unsigned)((fr + 64) * ROWB + fp * 16);

    const __half* FA0 = g_Fh + ((size_t)(b * HD + d0 + fr)) * NS + fp * 8;
    const __half* FA1 = FA0 + (size_t)64 * NS;
    const __half* PH0 = g_Ph + ((size_t)b * GPTS + g0 + fr) * NS + fp * 8;
    const __half* PH1 = PH0 + (size_t)64 * NS;
    const __half* PL0 = g_Pl + ((size_t)b * GPTS + g0 + fr) * NS + fp * 8;
    const __half* PL1 = PL0 + (size_t)64 * NS;

    const int NC = NS / GBK;   // 32

#pragma unroll
    for (int p = 0; p < 2; p++) {
        const unsigned sn = sb + (unsigned)(p * GST);
        const int sc = p * GBK;
        cpa16(sn + GA_H + dst0, FA0 + sc);
        cpa16(sn + GA_H + dst1, FA1 + sc);
        cpa16(sn + GB_H + dst0, PH0 + sc);
        cpa16(sn + GB_H + dst1, PH1 + sc);
        cpa16(sn + GB_L + dst0, PL0 + sc);
        cpa16(sn + GB_L + dst1, PL1 + sc);
        asm volatile("cp.async.commit_group;");
    }

    float acc[4][4][4];
#pragma unroll
    for (int i = 0; i < 4; i++)
#pragma unroll
        for (int j = 0; j < 4; j++)
#pragma unroll
            for (int e = 0; e < 4; e++) acc[i][j][e] = 0.0f;

    const unsigned am_row = (unsigned)((lane & 7) + ((lane >> 3) & 1) * 8);
    const unsigned am_kh  = (unsigned)(lane >> 4);
    const unsigned bm_row = (unsigned)(((lane >> 4) & 1) * 8 + (lane & 7));
    const unsigned bm_kb  = (unsigned)(((lane >> 3) & 1) * 16);

    int stage = 0;
#pragma unroll 1
    for (int c = 0; c < NC; c++) {
        const unsigned st = sb + (unsigned)(stage * GST);

        if (c + 1 < NC) asm volatile("cp.async.wait_group 1;");
        else            asm volatile("cp.async.wait_group 0;");
        __syncthreads();

        if (c + 2 < NC) {
            int pst = stage + 2; if (pst >= 3) pst -= 3;
            const unsigned sn = sb + (unsigned)(pst * GST);
            const int sc = (c + 2) * GBK;
            cpa16(sn + GA_H + dst0, FA0 + sc);
            cpa16(sn + GA_H + dst1, FA1 + sc);
            cpa16(sn + GB_H + dst0, PH0 + sc);
            cpa16(sn + GB_H + dst1, PH1 + sc);
            cpa16(sn + GB_L + dst0, PL0 + sc);
            cpa16(sn + GB_L + dst1, PL1 + sc);
            asm volatile("cp.async.commit_group;");
        }

#pragma unroll
        for (int kk = 0; kk < 2; kk++) {
            const unsigned kb = (unsigned)(kk * 16 + am_kh * 8) * 2;

            unsigned ah[4][4];
#pragma unroll
            for (int i = 0; i < 4; i++) {
                const unsigned rowoff = (unsigned)(wm * 64 + i * 16) + am_row;
                ldsm4(ah[i], st + GA_H + rowoff * ROWB + kb);
            }

#pragma unroll
            for (int jp = 0; jp < 2; jp++) {
                const unsigned brow = (unsigned)(wn * 32 + jp * 16) + bm_row;
                const unsigned bcol = (unsigned)(kk * 32) + bm_kb;
                unsigned bh[4], bl[4];
                ldsm4(bh, st + GB_H + brow * ROWB + bcol);
                ldsm4(bl, st + GB_L + brow * ROWB + bcol);
#pragma unroll
                for (int jj = 0; jj < 2; jj++) {
                    const int j = jp * 2 + jj;
#pragma unroll
                    for (int i = 0; i < 4; i++) {
                        mma16816(acc[i][j], ah[i], bh[2*jj], bh[2*jj+1]);
                        mma16816(acc[i][j], ah[i], bl[2*jj], bl[2*jj+1]);
                    }
                }
            }
        }

        if (++stage >= 3) stage = 0;
    }

    // epilogue: out[b][d][g]
    float* ob = out + (size_t)b * HD * GPTS;
#pragma unroll
    for (int i = 0; i < 4; i++) {
        const int d_r = d0 + wm * 64 + i * 16 + gid;
#pragma unroll
        for (int j = 0; j < 4; j++) {
            const int g_c = g0 + wn * 32 + j * 8 + tig * 2;
            *(float2*)(ob + (size_t)d_r * GPTS + g_c) =
                make_float2(acc[i][j][0], acc[i][j][1]);
            *(float2*)(ob + (size_t)(d_r + 8) * GPTS + g_c) =
                make_float2(acc[i][j][2], acc[i][j][3]);
        }
    }
}

// ---------------------------------------------------------------------------
// kernel_launch — single stream.
// Inputs: station_features, station_coords, mask, W1, b1, W2, b2
// ---------------------------------------------------------------------------
extern "C" void kernel_launch(void* const* d_in, const int* in_sizes, int n_in,
                              void* d_out, int out_size)
{
    const float* features = (const float*)d_in[0];  // [2,1024,256]
    const float* coords   = (const float*)d_in[1];  // [2,1024,3]
    const float* mask     = (const float*)d_in[2];  // [2,1024]
    const float* W1       = (const float*)d_in[3];  // [3,32]
    const float* b1       = (const float*)d_in[4];  // [32]
    const float* W2       = (const float*)d_in[5];  // [32,1]
    const float* b2       = (const float*)d_in[6];  // [1]
    float* out            = (float*)d_out;          // [2,256,64,128]

    static bool attr_set = false;
    if (!attr_set) {
        cudaFuncSetAttribute(hmma_gemm_kernel,
                             cudaFuncAttributeMaxDynamicSharedMemorySize, GSM_TOTAL);
        attr_set = true;
    }

    dim3 gf(NS / 64, HD / 64, NB);
    fsplit_kernel<<<gf, 256>>>(features);

    dim3 g1(GPTS / 32, NB);
    weights_kernel<<<g1, 256>>>(coords, mask, W1, b1, W2, b2);

    dim3 g2(GPTS / 128, HD / 128, NB);
    hmma_gemm_kernel<<<g2, 256, GSM_TOTAL>>>(out);
}

// round 12
// speedup vs baseline: 1.1467x; 1.0929x over previous
#include <cuda_runtime.h>
#include <cuda_fp16.h>
#include <math.h>
#include <float.h>

#define NLAT 64
#define NLON 128
#define GPTS 8192   // NLAT*NLON
#define NS   1024   // stations
#define HD   256    // hidden dim
#define NB   2      // batch

// fp32 logits, [b][g][s]
__device__ float g_L[(size_t)NB * GPTS * NS];
// fp16 normalized weights, [b][g][s]
__device__ __half g_Ph[(size_t)NB * GPTS * NS];
// fp16 transposed features, [b][d][s]
__device__ __half g_Fh[(size_t)NB * HD * NS];

// ---------------------------------------------------------------------------
// helpers
// ---------------------------------------------------------------------------
__device__ __forceinline__ float tanhap(float x)
{ float t; asm("tanh.approx.f32 %0, %1;" : "=f"(t) : "f"(x)); return t; }

__device__ __forceinline__ float sqrtap(float x)
{ float r; asm("sqrt.approx.f32 %0, %1;" : "=f"(r) : "f"(x)); return r; }

__device__ __forceinline__ unsigned smem_u32(const void* p)
{
    unsigned a;
    asm("{ .reg .u64 t; cvta.to.shared.u64 t, %1; cvt.u32.u64 %0, t; }"
        : "=r"(a) : "l"(p));
    return a;
}

__device__ __forceinline__ unsigned long long pack4(unsigned short a, unsigned short b,
                                                    unsigned short c, unsigned short d)
{
    return (unsigned long long)a | ((unsigned long long)b << 16)
         | ((unsigned long long)c << 32) | ((unsigned long long)d << 48);
}

// nonlinear GELU contribution: y*tanh(u) with y = z*v
__device__ __forceinline__ void unit_eval(float dist, float dlon,
                                          float w0, float wo, float a, float v,
                                          float& acc)
{
    const float z  = fmaf(dist, w0, fmaf(dlon, wo, a));
    const float y  = z * v;
    const float z2 = z * z;
    const float u  = z * fmaf(z2, 0.0356774081f, 0.7978845608f);
    acc = fmaf(y, tanhap(u), acc);
}

// ---------------------------------------------------------------------------
// F transpose: F[b][s][d] fp32 -> Fh [b][d][s] fp16.
// ---------------------------------------------------------------------------
__global__ __launch_bounds__(256) void fsplit_kernel(const float* __restrict__ F)
{
    __shared__ float tile[64][65];
    const int t  = threadIdx.x;
    const int s0 = blockIdx.x * 64;
    const int d0 = blockIdx.y * 64;
    const int b  = blockIdx.z;

#pragma unroll
    for (int q = 0; q < 4; q++) {
        const int idx   = q * 256 + t;
        const int s_loc = idx >> 4;
        const int d4    = (idx & 15) * 4;
        const float4 v = *(const float4*)(F + ((size_t)(b * NS + s0 + s_loc)) * HD + d0 + d4);
        tile[s_loc][d4 + 0] = v.x;
        tile[s_loc][d4 + 1] = v.y;
        tile[s_loc][d4 + 2] = v.z;
        tile[s_loc][d4 + 3] = v.w;
    }
    __syncthreads();

#pragma unroll
    for (int q = 0; q < 4; q++) {
        const int idx   = q * 256 + t;
        const int d_loc = idx >> 4;
        const int s4    = (idx & 15) * 4;
        unsigned short h[4];
#pragma unroll
        for (int e = 0; e < 4; e++)
            h[e] = __half_as_ushort(__float2half_rn(tile[s4 + e][d_loc]));
        const size_t off = ((size_t)(b * HD + d0 + d_loc)) * NS + s0 + s4;
        *(unsigned long long*)(g_Fh + off) = pack4(h[0], h[1], h[2], h[3]);
    }
}

// ---------------------------------------------------------------------------
// Phase 1: logits + fused online softmax.
// Grid (GPTS/32, NB), 256 threads = 8 warps.
// ---------------------------------------------------------------------------
__global__ __launch_bounds__(256) void weights_kernel(
    const float* __restrict__ coords,   // [B, S, 3]
    const float* __restrict__ mask,     // [B, S]
    const float* __restrict__ W1,       // [3, 32]
    const float* __restrict__ b1,       // [32]
    const float* __restrict__ W2,       // [32, 1]
    const float* __restrict__ b2)       // [1]
{
    __shared__ __align__(16) float sW0[32];
    __shared__ __align__(16) float sWa[32];
    __shared__ __align__(16) float sWo[32];
    __shared__ __align__(16) float sB1[32];
    __shared__ __align__(16) float sV[32];           // W2/2
    __shared__ __align__(16) float sA[8][2][2][32];  // [warp][buf][station][unit]
    __shared__ float sLat[NS];
    __shared__ float sLon[NS];
    __shared__ float sMask[NS];
    __shared__ float sS0, sSa, sSo, sSbb;
    __shared__ float red_m[8][32];
    __shared__ float red_s[8][32];
    __shared__ float sT[8][32][33];
    __shared__ float sMax[32];
    __shared__ float sInv[32];

    const int tid  = threadIdx.x;
    const int lane = tid & 31;
    const int wrp  = tid >> 5;
    const int b    = blockIdx.y;
    const int g0   = blockIdx.x * 32;
    const size_t bG = (size_t)b * GPTS;

    if (tid < 32) {
        sW0[tid] = W1[tid];
        sWa[tid] = W1[32 + tid];
        sWo[tid] = W1[64 + tid];
        sB1[tid] = b1[tid];
        sV[tid]  = 0.5f * W2[tid];
    }

    for (int s = tid; s < NS; s += 256) {
        sLat[s]  = coords[((size_t)b * NS + s) * 3 + 0];
        sLon[s]  = coords[((size_t)b * NS + s) * 3 + 1];
        sMask[s] = mask[(size_t)b * NS + s];
    }
    __syncthreads();

    if (wrp == 0) {
        const float v = sV[lane];
        float p0 = sW0[lane] * v;
        float pa = sWa[lane] * v;
        float po = sWo[lane] * v;
        float pb = sB1[lane] * v;
#pragma unroll
        for (int off = 16; off > 0; off >>= 1) {
            p0 += __shfl_xor_sync(0xffffffffu, p0, off);
            pa += __shfl_xor_sync(0xffffffffu, pa, off);
            po += __shfl_xor_sync(0xffffffffu, po, off);
            pb += __shfl_xor_sync(0xffffffffu, pb, off);
        }
        if (lane == 0) {
            sS0 = p0; sSa = pa; sSo = po; sSbb = pb + b2[0];
        }
    }
    __syncthreads();

    const int g = g0 + lane;
    const float glat = -90.0f  + (float)(g >> 7)  * (180.0f / 63.0f);  // warp-uniform
    const float glon = -180.0f + (float)(g & 127) * (360.0f / 127.0f);

    const float S0v = sS0, Sav = sSa, Sov = sSo, Sbb = sSbb;
    const float wa_l = sWa[lane];
    const float b1_l = sB1[lane];

    float m_run = -FLT_MAX;
    float s_run = 0.0f;
    const int s_base = wrp * 128;

#pragma unroll 1
    for (int it = 0; it < 128; it += 2) {
        const int s0 = s_base + it;
        const int s1 = s0 + 1;
        const int buf = (it >> 1) & 1;

        const float dlat0 = sLat[s0] - glat;
        const float dlon0 = sLon[s0] - glon;
        const float dist0 = sqrtap(fmaf(dlat0, dlat0, fmaf(dlon0, dlon0, 1e-6f)));
        const float dlat1 = sLat[s1] - glat;
        const float dlon1 = sLon[s1] - glon;
        const float dist1 = sqrtap(fmaf(dlat1, dlat1, fmaf(dlon1, dlon1, 1e-6f)));

        sA[wrp][buf][0][lane] = fmaf(dlat0, wa_l, b1_l);
        sA[wrp][buf][1][lane] = fmaf(dlat1, wa_l, b1_l);
        __syncwarp();

        float acc0 = 0.0f;
        float acc1 = 0.0f;
        const float lin0 = fmaf(dist0, S0v, fmaf(dlon0, Sov, fmaf(dlat0, Sav, Sbb)));
        const float lin1 = fmaf(dist1, S0v, fmaf(dlon1, Sov, fmaf(dlat1, Sav, Sbb)));

#pragma unroll
        for (int q = 0; q < 8; q++) {
            const float4 w0 = *(const float4*)&sW0[4 * q];
            const float4 wo = *(const float4*)&sWo[4 * q];
            const float4 vv = *(const float4*)&sV[4 * q];
            const float4 a0 = *(const float4*)&sA[wrp][buf][0][4 * q];
            const float4 a1 = *(const float4*)&sA[wrp][buf][1][4 * q];

            unit_eval(dist0, dlon0, w0.x, wo.x, a0.x, vv.x, acc0);
            unit_eval(dist0, dlon0, w0.y, wo.y, a0.y, vv.y, acc0);
            unit_eval(dist0, dlon0, w0.z, wo.z, a0.z, vv.z, acc0);
            unit_eval(dist0, dlon0, w0.w, wo.w, a0.w, vv.w, acc0);

            unit_eval(dist1, dlon1, w0.x, wo.x, a1.x, vv.x, acc1);
            unit_eval(dist1, dlon1, w0.y, wo.y, a1.y, vv.y, acc1);
            unit_eval(dist1, dlon1, w0.z, wo.z, a1.z, vv.z, acc1);
            unit_eval(dist1, dlon1, w0.w, wo.w, a1.w, vv.w, acc1);
        }

        const float pre0 = lin0 + acc0;
        const float pre1 = lin1 + acc1;

        const float sp0 = fmaxf(pre0, 0.0f) + __logf(1.0f + __expf(-fabsf(pre0)));
        const float sp1 = fmaxf(pre1, 0.0f) + __logf(1.0f + __expf(-fabsf(pre1)));
        const float l0  = sp0 * sMask[s0];
        const float l1  = sp1 * sMask[s1];

        const float mnew = fmaxf(m_run, fmaxf(l0, l1));
        s_run = fmaf(s_run, __expf(m_run - mnew),
                     __expf(l0 - mnew) + __expf(l1 - mnew));
        m_run = mnew;

        const int c0 = it & 31;
        sT[wrp][lane][c0]     = l0;
        sT[wrp][lane][c0 + 1] = l1;

        if (c0 == 30) {
            __syncwarp();
            const int sblk = s_base + (it & ~31);
#pragma unroll
            for (int r = 0; r < 32; r++)
                g_L[(bG + g0 + r) * NS + sblk + lane] = sT[wrp][r][lane];
            __syncwarp();
        }
    }

    red_m[wrp][lane] = m_run;
    red_s[wrp][lane] = s_run;
    __syncthreads();

    float M = -FLT_MAX;
#pragma unroll
    for (int w = 0; w < 8; w++) M = fmaxf(M, red_m[w][lane]);
    float Stot = 0.0f;
#pragma unroll
    for (int w = 0; w < 8; w++) Stot += red_s[w][lane] * __expf(red_m[w][lane] - M);

    if (wrp == 0) {
        sMax[lane] = M;
        sInv[lane] = 1.0f / Stot;
    }
    __syncthreads();

    // normalize pass: each warp handles 4 g-rows; emit fp16 [g][s].
#pragma unroll 1
    for (int k = 0; k < 4; k++) {
        const int r  = wrp + 8 * k;
        const float Mr   = sMax[r];
        const float invr = sInv[r];
        const size_t row = (bG + g0 + r) * NS;
#pragma unroll
        for (int cc = 0; cc < 8; cc++) {
            const int s4 = cc * 128 + lane * 4;
            const float4 v = *(const float4*)(g_L + row + s4);
            unsigned short h[4];
            h[0] = __half_as_ushort(__float2half_rn(__expf(v.x - Mr) * invr));
            h[1] = __half_as_ushort(__float2half_rn(__expf(v.y - Mr) * invr));
            h[2] = __half_as_ushort(__float2half_rn(__expf(v.z - Mr) * invr));
            h[3] = __half_as_ushort(__float2half_rn(__expf(v.w - Mr) * invr));
            *(unsigned long long*)(g_Ph + row + s4) = pack4(h[0], h[1], h[2], h[3]);
        }
    }
}

// ---------------------------------------------------------------------------
// Phase 2: single-product fp16 HMMA GEMM (Fh*Ph), 4-stage cp.async.
// Block: 128d x 128g x BK32, 256 threads (8 warps), warp tile 64d x 32g.
// __launch_bounds__(256, 2): 2 CTAs/SM; smem 2 x 80KB = 160KB fits.
// Grid (GPTS/128, HD/128, NB) = 256 CTAs.
// ---------------------------------------------------------------------------
#define GBK   32
#define ROWB  80
#define GA_H  0
#define GB_H  10240
#define GST   20480
#define GSTAGES 4
#define GSM_TOTAL (GSTAGES * GST)

__device__ __forceinline__ void cpa16(unsigned dst, const void* src)
{
    asm volatile("cp.async.cg.shared.global [%0], [%1], 16;"
                 :: "r"(dst), "l"(__cvta_generic_to_global(src)));
}

__device__ __forceinline__ void ldsm4(unsigned* r, unsigned addr)
{
    asm volatile("ldmatrix.sync.aligned.m8n8.x4.shared.b16 {%0,%1,%2,%3}, [%4];"
                 : "=r"(r[0]), "=r"(r[1]), "=r"(r[2]), "=r"(r[3]) : "r"(addr));
}

__device__ __forceinline__ void mma16816(float* c, const unsigned* a, unsigned b0, unsigned b1)
{
    asm volatile(
        "mma.sync.aligned.m16n8k16.row.col.f32.f16.f16.f32 "
        "{%0,%1,%2,%3}, {%4,%5,%6,%7}, {%8,%9}, {%0,%1,%2,%3};"
        : "+f"(c[0]), "+f"(c[1]), "+f"(c[2]), "+f"(c[3])
        : "r"(a[0]), "r"(a[1]), "r"(a[2]), "r"(a[3]), "r"(b0), "r"(b1));
}

__global__ __launch_bounds__(256, 2) void hmma_gemm_kernel(float* __restrict__ out)
{
    extern __shared__ __align__(16) char smem[];
    const unsigned sb = smem_u32(smem);

    const int t    = threadIdx.x;
    const int wid  = t >> 5;
    const int lane = t & 31;
    const int g0   = blockIdx.x * 128;
    const int d0   = blockIdx.y * 128;
    const int b    = blockIdx.z;

    const int wm = wid & 1;        // d half (64)
    const int wn = wid >> 1;       // g slice of 32 (0..3)
    const int gid = lane >> 2;
    const int tig = lane & 3;

    // fill mapping: 512 16B-chunks per tile, 2 per thread (rows fr, fr+64)
    const int fr = t >> 2;         // 0..63
    const int fp = t & 3;          // 0..3
    const unsigned dst0 = (unsigned)(fr * ROWB + fp * 16);
    const unsigned dst1 = (unsigned)((fr + 64) * ROWB + fp * 16);

    const __half* FA0 = g_Fh + ((size_t)(b * HD + d0 + fr)) * NS + fp * 8;
    const __half* FA1 = FA0 + (size_t)64 * NS;
    const __half* PH0 = g_Ph + ((size_t)b * GPTS + g0 + fr) * NS + fp * 8;
    const __half* PH1 = PH0 + (size_t)64 * NS;

    const int NC = NS / GBK;   // 32

    // prologue: fill stages 0..2 (chunks 0..2)
#pragma unroll
    for (int p = 0; p < GSTAGES - 1; p++) {
        const unsigned sn = sb + (unsigned)(p * GST);
        const int sc = p * GBK;
        cpa16(sn + GA_H + dst0, FA0 + sc);
        cpa16(sn + GA_H + dst1, FA1 + sc);
        cpa16(sn + GB_H + dst0, PH0 + sc);
        cpa16(sn + GB_H + dst1, PH1 + sc);
        asm volatile("cp.async.commit_group;");
    }

    float acc[4][4][4];
#pragma unroll
    for (int i = 0; i < 4; i++)
#pragma unroll
        for (int j = 0; j < 4; j++)
#pragma unroll
            for (int e = 0; e < 4; e++) acc[i][j][e] = 0.0f;

    const unsigned am_row = (unsigned)((lane & 7) + ((lane >> 3) & 1) * 8);
    const unsigned am_kh  = (unsigned)(lane >> 4);
    const unsigned bm_row = (unsigned)(((lane >> 4) & 1) * 8 + (lane & 7));
    const unsigned bm_kb  = (unsigned)(((lane >> 3) & 1) * 16);

    int stage = 0;
#pragma unroll 1
    for (int c = 0; c < NC; c++) {
        const unsigned st = sb + (unsigned)(stage * GST);

        if (c + 1 < NC) asm volatile("cp.async.wait_group %0;" :: "n"(GSTAGES - 2));
        else            asm volatile("cp.async.wait_group 0;");
        __syncthreads();

        if (c + GSTAGES - 1 < NC) {
            int pst = stage + GSTAGES - 1; if (pst >= GSTAGES) pst -= GSTAGES;
            const unsigned sn = sb + (unsigned)(pst * GST);
            const int sc = (c + GSTAGES - 1) * GBK;
            cpa16(sn + GA_H + dst0, FA0 + sc);
            cpa16(sn + GA_H + dst1, FA1 + sc);
            cpa16(sn + GB_H + dst0, PH0 + sc);
            cpa16(sn + GB_H + dst1, PH1 + sc);
            asm volatile("cp.async.commit_group;");
        }

#pragma unroll
        for (int kk = 0; kk < 2; kk++) {
            const unsigned kb = (unsigned)(kk * 16 + am_kh * 8) * 2;

            unsigned ah[4][4];
#pragma unroll
            for (int i = 0; i < 4; i++) {
                const unsigned rowoff = (unsigned)(wm * 64 + i * 16) + am_row;
                ldsm4(ah[i], st + GA_H + rowoff * ROWB + kb);
            }

#pragma unroll
            for (int jp = 0; jp < 2; jp++) {
                const unsigned brow = (unsigned)(wn * 32 + jp * 16) + bm_row;
                const unsigned bcol = (unsigned)(kk * 32) + bm_kb;
                unsigned bh[4];
                ldsm4(bh, st + GB_H + brow * ROWB + bcol);
#pragma unroll
                for (int jj = 0; jj < 2; jj++) {
                    const int j = jp * 2 + jj;
#pragma unroll
                    for (int i = 0; i < 4; i++)
                        mma16816(acc[i][j], ah[i], bh[2*jj], bh[2*jj+1]);
                }
            }
        }

        if (++stage >= GSTAGES) stage = 0;
    }

    // epilogue: out[b][d][g]
    float* ob = out + (size_t)b * HD * GPTS;
#pragma unroll
    for (int i = 0; i < 4; i++) {
        const int d_r = d0 + wm * 64 + i * 16 + gid;
#pragma unroll
        for (int j = 0; j < 4; j++) {
            const int g_c = g0 + wn * 32 + j * 8 + tig * 2;
            *(float2*)(ob + (size_t)d_r * GPTS + g_c) =
                make_float2(acc[i][j][0], acc[i][j][1]);
            *(float2*)(ob + (size_t)(d_r + 8) * GPTS + g_c) =
                make_float2(acc[i][j][2], acc[i][j][3]);
        }
    }
}

// ---------------------------------------------------------------------------
// kernel_launch — single stream.
// Inputs: station_features, station_coords, mask, W1, b1, W2, b2
// ---------------------------------------------------------------------------
extern "C" void kernel_launch(void* const* d_in, const int* in_sizes, int n_in,
                              void* d_out, int out_size)
{
    const float* features = (const float*)d_in[0];  // [2,1024,256]
    const float* coords   = (const float*)d_in[1];  // [2,1024,3]
    const float* mask     = (const float*)d_in[2];  // [2,1024]
    const float* W1       = (const float*)d_in[3];  // [3,32]
    const float* b1       = (const float*)d_in[4];  // [32]
    const float* W2       = (const float*)d_in[5];  // [32,1]
    const float* b2       = (const float*)d_in[6];  // [1]
    float* out            = (float*)d_out;          // [2,256,64,128]

    static bool attr_set = false;
    if (!attr_set) {
        cudaFuncSetAttribute(hmma_gemm_kernel,
                             cudaFuncAttributeMaxDynamicSharedMemorySize, GSM_TOTAL);
        attr_set = true;
    }

    dim3 gf(NS / 64, HD / 64, NB);
    fsplit_kernel<<<gf, 256>>>(features);

    dim3 g1(GPTS / 32, NB);
    weights_kernel<<<g1, 256>>>(coords, mask, W1, b1, W2, b2);

    dim3 g2(GPTS / 128, HD / 128, NB);
    hmma_gemm_kernel<<<g2, 256, GSM_TOTAL>>>(out);
}